// round 1
// baseline (speedup 1.0000x reference)
#include <cuda_runtime.h>
#include <math.h>

#define BB 32
#define PP 8732
#define MM 16
#define CC 81
#define THRESH 0.5f

// Scratch (no allocation allowed -> __device__ globals)
__device__ float g_negloss[BB * PP];
__device__ int   g_label[BB * PP];
__device__ int   g_npos[BB];
__device__ float g_acc[3];     // 0: loc_sum, 1: pos_conf_sum, 2: hard_neg_sum
__device__ int   g_npos_total;

__global__ void init_kernel() {
    g_acc[0] = 0.f; g_acc[1] = 0.f; g_acc[2] = 0.f;
    g_npos_total = 0;
}

// One block per image. Phase 1: per-object argmax over priors (original IoU matrix).
// Phase 2: per-prior argmax over objects + forced matches, labels, loc loss.
__global__ void match_kernel(const float* __restrict__ locs,
                             const float* __restrict__ boxes,
                             const int*   __restrict__ labels,
                             const float* __restrict__ priors) {
    const int b   = blockIdx.x;
    const int tid = threadIdx.x;

    __shared__ float s_box[MM][4];
    __shared__ float s_area[MM];
    __shared__ int   s_lab[MM];
    __shared__ int   s_pfo[MM];          // prior_for_each_object
    __shared__ float red_iou[MM][8];
    __shared__ int   red_p[MM][8];
    __shared__ float s_redf[256];
    __shared__ int   s_redi[256];

    if (tid < MM) {
        float x0 = boxes[(b * MM + tid) * 4 + 0];
        float y0 = boxes[(b * MM + tid) * 4 + 1];
        float x1 = boxes[(b * MM + tid) * 4 + 2];
        float y1 = boxes[(b * MM + tid) * 4 + 3];
        s_box[tid][0] = x0; s_box[tid][1] = y0;
        s_box[tid][2] = x1; s_box[tid][3] = y1;
        s_area[tid] = (x1 - x0) * (y1 - y0);
        s_lab[tid]  = labels[b * MM + tid];
    }
    __syncthreads();

    // ---- Phase 1: for each object m, argmax IoU over all priors p ----
    float biou[MM];
    int   bp[MM];
#pragma unroll
    for (int m = 0; m < MM; m++) { biou[m] = -1.f; bp[m] = 0x7fffffff; }

    for (int p = tid; p < PP; p += 256) {
        float pcx = priors[p * 4 + 0], pcy = priors[p * 4 + 1];
        float pw  = priors[p * 4 + 2], ph  = priors[p * 4 + 3];
        float px0 = pcx - pw * 0.5f, py0 = pcy - ph * 0.5f;
        float px1 = pcx + pw * 0.5f, py1 = pcy + ph * 0.5f;
        float parea = (px1 - px0) * (py1 - py0);
#pragma unroll
        for (int m = 0; m < MM; m++) {
            float ix0 = fmaxf(s_box[m][0], px0);
            float iy0 = fmaxf(s_box[m][1], py0);
            float ix1 = fminf(s_box[m][2], px1);
            float iy1 = fminf(s_box[m][3], py1);
            float iw  = fmaxf(ix1 - ix0, 0.f);
            float ih  = fmaxf(iy1 - iy0, 0.f);
            float inter = iw * ih;
            float iou = inter / (s_area[m] + parea - inter);
            if (iou > biou[m]) { biou[m] = iou; bp[m] = p; }  // strict >: keeps lowest p
        }
    }

    const int lane = tid & 31, warp = tid >> 5;
#pragma unroll
    for (int m = 0; m < MM; m++) {
        float v = biou[m]; int ip = bp[m];
        for (int o = 16; o > 0; o >>= 1) {
            float ov = __shfl_down_sync(0xffffffffu, v, o);
            int   op = __shfl_down_sync(0xffffffffu, ip, o);
            if (ov > v || (ov == v && op < ip)) { v = ov; ip = op; }
        }
        if (lane == 0) { red_iou[m][warp] = v; red_p[m][warp] = ip; }
    }
    __syncthreads();
    if (tid < MM) {
        float v = red_iou[tid][0]; int ip = red_p[tid][0];
        for (int w = 1; w < 8; w++) {
            float ov = red_iou[tid][w]; int op = red_p[tid][w];
            if (ov > v || (ov == v && op < ip)) { v = ov; ip = op; }
        }
        s_pfo[tid] = ip;
    }
    __syncthreads();

    // ---- Phase 2: per-prior best object + forced matches, label, loc loss ----
    float locsum = 0.f;
    int   posc   = 0;
    for (int p = tid; p < PP; p += 256) {
        float pcx = priors[p * 4 + 0], pcy = priors[p * 4 + 1];
        float pw  = priors[p * 4 + 2], ph  = priors[p * 4 + 3];
        float px0 = pcx - pw * 0.5f, py0 = pcy - ph * 0.5f;
        float px1 = pcx + pw * 0.5f, py1 = pcy + ph * 0.5f;
        float parea = (px1 - px0) * (py1 - py0);

        float best = -1.f; int obj = 0;
#pragma unroll
        for (int m = 0; m < MM; m++) {
            float ix0 = fmaxf(s_box[m][0], px0);
            float iy0 = fmaxf(s_box[m][1], py0);
            float ix1 = fminf(s_box[m][2], px1);
            float iy1 = fminf(s_box[m][3], py1);
            float iw  = fmaxf(ix1 - ix0, 0.f);
            float ih  = fmaxf(iy1 - iy0, 0.f);
            float inter = iw * ih;
            float iou = inter / (s_area[m] + parea - inter);
            if (iou > best) { best = iou; obj = m; }  // strict >: lowest m on ties
        }
        // Forced matches: ascending m, last wins (matches scatter order)
#pragma unroll
        for (int m = 0; m < MM; m++) {
            if (s_pfo[m] == p) { obj = m; best = 1.0f; }
        }
        int lab = (best < THRESH) ? 0 : s_lab[obj];
        g_label[b * PP + p] = lab;

        if (lab != 0) {
            posc++;
            float bx0 = s_box[obj][0], by0 = s_box[obj][1];
            float bx1 = s_box[obj][2], by1 = s_box[obj][3];
            float cx = (bx0 + bx1) * 0.5f, cy = (by0 + by1) * 0.5f;
            float cw = bx1 - bx0, ch = by1 - by0;
            float g0 = (cx - pcx) * 10.f / pw;
            float g1 = (cy - pcy) * 10.f / ph;
            float g2 = logf(cw / pw) * 5.f;
            float g3 = logf(ch / ph) * 5.f;
            const float* pl = locs + ((size_t)(b * PP + p)) * 4;
            locsum += fabsf(pl[0] - g0) + fabsf(pl[1] - g1)
                    + fabsf(pl[2] - g2) + fabsf(pl[3] - g3);
        }
    }

    s_redf[tid] = locsum; s_redi[tid] = posc;
    __syncthreads();
    for (int s = 128; s > 0; s >>= 1) {
        if (tid < s) { s_redf[tid] += s_redf[tid + s]; s_redi[tid] += s_redi[tid + s]; }
        __syncthreads();
    }
    if (tid == 0) {
        atomicAdd(&g_acc[0], s_redf[0]);
        g_npos[b] = s_redi[0];
        atomicAdd(&g_npos_total, s_redi[0]);
    }
}

// One warp per prior: log-softmax over 81 classes, -logp[target].
__global__ void conf_kernel(const float* __restrict__ logits) {
    int w = blockIdx.x * 8 + (threadIdx.x >> 5);
    int lane = threadIdx.x & 31;
    if (w >= BB * PP) return;
    const float* row = logits + (size_t)w * CC;

    float x0 = row[lane];
    float x1 = row[lane + 32];
    float x2 = (lane < 17) ? row[lane + 64] : -INFINITY;

    float mx = fmaxf(fmaxf(x0, x1), x2);
    for (int o = 16; o > 0; o >>= 1)
        mx = fmaxf(mx, __shfl_xor_sync(0xffffffffu, mx, o));

    float s = expf(x0 - mx) + expf(x1 - mx) + ((lane < 17) ? expf(x2 - mx) : 0.f);
    for (int o = 16; o > 0; o >>= 1)
        s += __shfl_xor_sync(0xffffffffu, s, o);

    int lab = g_label[w];
    float xc = row[lab];
    float loss = -(xc - mx - logf(s));
    if (!isfinite(loss)) loss = 0.f;  // nan_to_num

    if (lane == 0) {
        if (lab != 0) {
            atomicAdd(&g_acc[1], loss);
            g_negloss[w] = 0.f;
        } else {
            g_negloss[w] = loss;
        }
    }
}

// One block per image: exact top-K sum via binary search on float bits.
__global__ void topk_kernel() {
    const int b = blockIdx.x, tid = threadIdx.x;
    __shared__ float s_val[PP];
    __shared__ int   s_cnt[256];
    __shared__ float s_sum[256];

    for (int p = tid; p < PP; p += 256) s_val[p] = g_negloss[b * PP + p];
    __syncthreads();

    int K = g_npos[b] * 3;
    if (K > PP) K = PP;
    if (K <= 0) return;  // contributes 0

    // Largest u with cnt_ge(float(u)) >= K. Values are all >= 0.
    unsigned lo = 0u, hi = 0x7f7fffffu;
    while (lo < hi) {
        unsigned mid = lo + ((hi - lo + 1u) >> 1);
        float t = __uint_as_float(mid);
        int c = 0;
        for (int p = tid; p < PP; p += 256) c += (s_val[p] >= t) ? 1 : 0;
        s_cnt[tid] = c;
        __syncthreads();
        for (int s = 128; s > 0; s >>= 1) {
            if (tid < s) s_cnt[tid] += s_cnt[tid + s];
            __syncthreads();
        }
        int total = s_cnt[0];
        __syncthreads();
        if (total >= K) lo = mid; else hi = mid - 1u;
    }
    float v = __uint_as_float(lo);

    int cgt = 0; float sgt = 0.f;
    for (int p = tid; p < PP; p += 256) {
        float x = s_val[p];
        if (x > v) { cgt++; sgt += x; }
    }
    s_cnt[tid] = cgt; s_sum[tid] = sgt;
    __syncthreads();
    for (int s = 128; s > 0; s >>= 1) {
        if (tid < s) { s_cnt[tid] += s_cnt[tid + s]; s_sum[tid] += s_sum[tid + s]; }
        __syncthreads();
    }
    if (tid == 0) {
        float res = s_sum[0] + (float)(K - s_cnt[0]) * v;
        atomicAdd(&g_acc[2], res);
    }
}

__global__ void final_kernel(float* out) {
    float n = (float)g_npos_total;
    out[0] = (g_acc[1] + g_acc[2]) / n + g_acc[0] / (4.f * n);
}

extern "C" void kernel_launch(void* const* d_in, const int* in_sizes, int n_in,
                              void* d_out, int out_size) {
    const float* locs   = (const float*)d_in[0];
    const float* logits = (const float*)d_in[1];
    const float* boxes  = (const float*)d_in[2];
    const int*   labels = (const int*)d_in[3];
    const float* priors = (const float*)d_in[4];
    float* out = (float*)d_out;

    init_kernel<<<1, 1>>>();
    match_kernel<<<BB, 256>>>(locs, boxes, labels, priors);
    conf_kernel<<<(BB * PP + 7) / 8, 256>>>(logits);
    topk_kernel<<<BB, 256>>>();
    final_kernel<<<1, 1>>>(out);
}

// round 2
// speedup vs baseline: 2.5254x; 2.5254x over previous
#include <cuda_runtime.h>
#include <math.h>

#define BB 32
#define PP 8732
#define MM 16
#define CC 81
#define THRESH 0.5f
#define NBLK 8
#define CH ((PP + NBLK - 1) / NBLK)   // 1092 priors per chunk

// Scratch (no allocation allowed -> __device__ globals)
__device__ unsigned long long g_pfo[BB * MM];  // packed (iou_bits<<32 | ~prior)
__device__ float g_negloss[BB * PP];
__device__ int   g_label[BB * PP];
__device__ int   g_npos[BB];
__device__ float g_acc[3];     // 0: loc_sum, 1: pos_conf_sum, 2: hard_neg_sum
__device__ int   g_npos_total;
__device__ int   g_done;

__global__ void init_kernel() {
    int t = threadIdx.x;
    for (int i = t; i < BB * MM; i += 256) g_pfo[i] = 0ull;
    if (t < BB) g_npos[t] = 0;
    if (t == 0) {
        g_acc[0] = 0.f; g_acc[1] = 0.f; g_acc[2] = 0.f;
        g_npos_total = 0; g_done = 0;
    }
}

// ---- match1: per-object argmax of IoU over priors, via packed atomicMax ----
__global__ void match1_kernel(const float* __restrict__ boxes,
                              const float* __restrict__ priors) {
    const int b = blockIdx.x / NBLK, c = blockIdx.x % NBLK;
    const int tid = threadIdx.x;

    __shared__ float s_box[MM][4];
    __shared__ float s_area[MM];
    __shared__ unsigned long long s_red[MM][8];

    if (tid < MM) {
        float x0 = boxes[(b * MM + tid) * 4 + 0];
        float y0 = boxes[(b * MM + tid) * 4 + 1];
        float x1 = boxes[(b * MM + tid) * 4 + 2];
        float y1 = boxes[(b * MM + tid) * 4 + 3];
        s_box[tid][0] = x0; s_box[tid][1] = y0;
        s_box[tid][2] = x1; s_box[tid][3] = y1;
        s_area[tid] = (x1 - x0) * (y1 - y0);
    }
    __syncthreads();

    const int p0 = c * CH;
    const int p1 = (p0 + CH < PP) ? p0 + CH : PP;

    float biou[MM];
    int   bp[MM];
#pragma unroll
    for (int m = 0; m < MM; m++) { biou[m] = -1.f; bp[m] = 0; }

    for (int p = p0 + tid; p < p1; p += 256) {
        float pcx = priors[p * 4 + 0], pcy = priors[p * 4 + 1];
        float pw  = priors[p * 4 + 2], ph  = priors[p * 4 + 3];
        float px0 = pcx - pw * 0.5f, py0 = pcy - ph * 0.5f;
        float px1 = pcx + pw * 0.5f, py1 = pcy + ph * 0.5f;
        float parea = (px1 - px0) * (py1 - py0);
#pragma unroll
        for (int m = 0; m < MM; m++) {
            float ix0 = fmaxf(s_box[m][0], px0);
            float iy0 = fmaxf(s_box[m][1], py0);
            float ix1 = fminf(s_box[m][2], px1);
            float iy1 = fminf(s_box[m][3], py1);
            float iw  = fmaxf(ix1 - ix0, 0.f);
            float ih  = fmaxf(iy1 - iy0, 0.f);
            float inter = iw * ih;
            float iou = inter / (s_area[m] + parea - inter);
            if (iou > biou[m]) { biou[m] = iou; bp[m] = p; }  // strict >: lowest p
        }
    }

    const int lane = tid & 31, warp = tid >> 5;
#pragma unroll
    for (int m = 0; m < MM; m++) {
        // pack: higher iou wins; ties -> larger ~p == smaller p wins
        unsigned long long key = (biou[m] < 0.f) ? 0ull :
            (((unsigned long long)__float_as_uint(biou[m]) << 32) |
             (unsigned long long)(~(unsigned)bp[m]));
        for (int o = 16; o > 0; o >>= 1) {
            unsigned long long ok = __shfl_down_sync(0xffffffffu, key, o);
            if (ok > key) key = ok;
        }
        if (lane == 0) s_red[m][warp] = key;
    }
    __syncthreads();
    if (tid < MM) {
        unsigned long long key = s_red[tid][0];
        for (int w = 1; w < 8; w++)
            if (s_red[tid][w] > key) key = s_red[tid][w];
        atomicMax(&g_pfo[b * MM + tid], key);
    }
}

// ---- match2: per-prior best object + forced matches, labels, loc loss ----
__global__ void match2_kernel(const float* __restrict__ locs,
                              const float* __restrict__ boxes,
                              const int*   __restrict__ labels,
                              const float* __restrict__ priors) {
    const int b = blockIdx.x / NBLK, c = blockIdx.x % NBLK;
    const int tid = threadIdx.x;

    __shared__ float s_box[MM][4];
    __shared__ float s_area[MM];
    __shared__ int   s_lab[MM];
    __shared__ int   s_pfo[MM];
    __shared__ float s_redf[256];
    __shared__ int   s_redi[256];

    if (tid < MM) {
        float x0 = boxes[(b * MM + tid) * 4 + 0];
        float y0 = boxes[(b * MM + tid) * 4 + 1];
        float x1 = boxes[(b * MM + tid) * 4 + 2];
        float y1 = boxes[(b * MM + tid) * 4 + 3];
        s_box[tid][0] = x0; s_box[tid][1] = y0;
        s_box[tid][2] = x1; s_box[tid][3] = y1;
        s_area[tid] = (x1 - x0) * (y1 - y0);
        s_lab[tid]  = labels[b * MM + tid];
        s_pfo[tid]  = (int)(~(unsigned)(g_pfo[b * MM + tid] & 0xffffffffull));
    }
    __syncthreads();

    const int p0 = c * CH;
    const int p1 = (p0 + CH < PP) ? p0 + CH : PP;

    float locsum = 0.f;
    int   posc   = 0;
    for (int p = p0 + tid; p < p1; p += 256) {
        float pcx = priors[p * 4 + 0], pcy = priors[p * 4 + 1];
        float pw  = priors[p * 4 + 2], ph  = priors[p * 4 + 3];
        float px0 = pcx - pw * 0.5f, py0 = pcy - ph * 0.5f;
        float px1 = pcx + pw * 0.5f, py1 = pcy + ph * 0.5f;
        float parea = (px1 - px0) * (py1 - py0);

        float best = -1.f; int obj = 0;
#pragma unroll
        for (int m = 0; m < MM; m++) {
            float ix0 = fmaxf(s_box[m][0], px0);
            float iy0 = fmaxf(s_box[m][1], py0);
            float ix1 = fminf(s_box[m][2], px1);
            float iy1 = fminf(s_box[m][3], py1);
            float iw  = fmaxf(ix1 - ix0, 0.f);
            float ih  = fmaxf(iy1 - iy0, 0.f);
            float inter = iw * ih;
            float iou = inter / (s_area[m] + parea - inter);
            if (iou > best) { best = iou; obj = m; }  // lowest m on ties
        }
        // forced matches: ascending m, last wins (scatter semantics)
#pragma unroll
        for (int m = 0; m < MM; m++) {
            if (s_pfo[m] == p) { obj = m; best = 1.0f; }
        }
        int lab = (best < THRESH) ? 0 : s_lab[obj];
        g_label[b * PP + p] = lab;

        if (lab != 0) {
            posc++;
            float bx0 = s_box[obj][0], by0 = s_box[obj][1];
            float bx1 = s_box[obj][2], by1 = s_box[obj][3];
            float cx = (bx0 + bx1) * 0.5f, cy = (by0 + by1) * 0.5f;
            float cw = bx1 - bx0, ch = by1 - by0;
            float g0 = (cx - pcx) * 10.f / pw;
            float g1 = (cy - pcy) * 10.f / ph;
            float g2 = logf(cw / pw) * 5.f;
            float g3 = logf(ch / ph) * 5.f;
            const float* pl = locs + ((size_t)(b * PP + p)) * 4;
            locsum += fabsf(pl[0] - g0) + fabsf(pl[1] - g1)
                    + fabsf(pl[2] - g2) + fabsf(pl[3] - g3);
        }
    }

    s_redf[tid] = locsum; s_redi[tid] = posc;
    __syncthreads();
    for (int s = 128; s > 0; s >>= 1) {
        if (tid < s) { s_redf[tid] += s_redf[tid + s]; s_redi[tid] += s_redi[tid + s]; }
        __syncthreads();
    }
    if (tid == 0) {
        if (s_redf[0] != 0.f) atomicAdd(&g_acc[0], s_redf[0]);
        if (s_redi[0] != 0)   { atomicAdd(&g_npos[b], s_redi[0]);
                                atomicAdd(&g_npos_total, s_redi[0]); }
    }
}

// ---- conf: warp per prior; log-softmax over 81 classes; block-reduced atomics ----
__global__ void conf_kernel(const float* __restrict__ logits) {
    const int w = blockIdx.x * 8 + (threadIdx.x >> 5);   // grid exact: BB*PP % 8 == 0
    const int lane = threadIdx.x & 31;
    const int warp = threadIdx.x >> 5;
    __shared__ float s_pos[8];

    const float* row = logits + (size_t)w * CC;
    float x0 = row[lane];
    float x1 = row[lane + 32];
    float x2 = (lane < 17) ? row[lane + 64] : -INFINITY;

    float mx = fmaxf(fmaxf(x0, x1), x2);
    for (int o = 16; o > 0; o >>= 1)
        mx = fmaxf(mx, __shfl_xor_sync(0xffffffffu, mx, o));

    float s = expf(x0 - mx) + expf(x1 - mx) + ((lane < 17) ? expf(x2 - mx) : 0.f);
    for (int o = 16; o > 0; o >>= 1)
        s += __shfl_xor_sync(0xffffffffu, s, o);

    int lab = g_label[w];
    float xc = (lab < 32) ? __shfl_sync(0xffffffffu, x0, lab)
             : (lab < 64) ? __shfl_sync(0xffffffffu, x1, lab - 32)
                          : __shfl_sync(0xffffffffu, x2, lab - 64);
    float loss = -(xc - mx - logf(s));
    if (!isfinite(loss)) loss = 0.f;  // nan_to_num

    if (lane == 0) {
        if (lab != 0) {
            s_pos[warp] = loss;
            g_negloss[w] = 0.f;
        } else {
            s_pos[warp] = 0.f;
            g_negloss[w] = loss;
        }
    }
    __syncthreads();
    if (threadIdx.x == 0) {
        float t = 0.f;
#pragma unroll
        for (int i = 0; i < 8; i++) t += s_pos[i];
        if (t != 0.f) atomicAdd(&g_acc[1], t);   // one atomic per block max
    }
}

// ---- topk: exact top-K sum via binary search on float bits; register-resident ----
#define NV ((PP + 255) / 256)   // 35
__global__ void topk_kernel(float* __restrict__ out) {
    const int b = blockIdx.x, tid = threadIdx.x;
    __shared__ int   s_total;
    __shared__ int   s_cnt[8];
    __shared__ float s_sum[8];

    float v[NV];
#pragma unroll
    for (int i = 0; i < NV; i++) {
        int p = tid + i * 256;
        v[i] = (p < PP) ? g_negloss[b * PP + p] : -1.f;   // pad never counts (t>=0)
    }

    int K = g_npos[b] * 3;
    if (K > PP) K = PP;

    if (K > 0) {
        unsigned lo = 0u, hi = 0x7f7fffffu;
        const int lane = tid & 31, warp = tid >> 5;
        while (lo < hi) {
            unsigned mid = lo + ((hi - lo + 1u) >> 1);
            float t = __uint_as_float(mid);
            int c = 0;
#pragma unroll
            for (int i = 0; i < NV; i++) c += (v[i] >= t) ? 1 : 0;
            c = __reduce_add_sync(0xffffffffu, c);
            if (tid == 0) s_total = 0;
            __syncthreads();
            if (lane == 0) atomicAdd(&s_total, c);
            __syncthreads();
            if (s_total >= K) lo = mid; else hi = mid - 1u;
        }
        float thr = __uint_as_float(lo);

        int cgt = 0; float sgt = 0.f;
#pragma unroll
        for (int i = 0; i < NV; i++) {
            float x = v[i];
            if (x > thr) { cgt++; sgt += x; }
        }
        cgt = __reduce_add_sync(0xffffffffu, cgt);
        for (int o = 16; o > 0; o >>= 1)
            sgt += __shfl_xor_sync(0xffffffffu, sgt, o);
        if (lane == 0) { s_cnt[warp] = cgt; s_sum[warp] = sgt; }
        __syncthreads();
        if (tid == 0) {
            int   tc = 0; float ts = 0.f;
#pragma unroll
            for (int i = 0; i < 8; i++) { tc += s_cnt[i]; ts += s_sum[i]; }
            atomicAdd(&g_acc[2], ts + (float)(K - tc) * thr);
        }
    }

    // fused final combine: last block writes the scalar result
    __syncthreads();
    if (tid == 0) {
        __threadfence();
        int prev = atomicAdd(&g_done, 1);
        if (prev == BB - 1) {
            float n = (float)g_npos_total;
            out[0] = (g_acc[1] + g_acc[2]) / n + g_acc[0] / (4.f * n);
        }
    }
}

extern "C" void kernel_launch(void* const* d_in, const int* in_sizes, int n_in,
                              void* d_out, int out_size) {
    const float* locs   = (const float*)d_in[0];
    const float* logits = (const float*)d_in[1];
    const float* boxes  = (const float*)d_in[2];
    const int*   labels = (const int*)d_in[3];
    const float* priors = (const float*)d_in[4];
    float* out = (float*)d_out;

    init_kernel<<<1, 256>>>();
    match1_kernel<<<BB * NBLK, 256>>>(boxes, priors);
    match2_kernel<<<BB * NBLK, 256>>>(locs, boxes, labels, priors);
    conf_kernel<<<(BB * PP) / 8, 256>>>(logits);
    topk_kernel<<<BB, 256>>>(out);
}